// round 1
// baseline (speedup 1.0000x reference)
#include <cuda_runtime.h>

#define DIM    192
#define HEADS  6
#define HD     32
#define NTOK   49
#define NWIN   64
#define STRIDE 193        // odd stride: conflict-free strided smem reads
#define ATS    50         // attn row stride

// smem floats: 4 tiles of 49*193 + attn 49*50
#define SMEM_FLOATS (4*NTOK*STRIDE + NTOK*ATS)

__global__ __launch_bounds__(192, 1)
void win_attn_kernel(const float* __restrict__ x,
                     const float* __restrict__ mask,
                     const float* __restrict__ qkv_w,
                     const float* __restrict__ qkv_b,
                     const float* __restrict__ proj_w,
                     const float* __restrict__ proj_b,
                     const float* __restrict__ bias_table,
                     const int*   __restrict__ rel_idx,
                     float* __restrict__ out)
{
    extern __shared__ float smem[];
    float* xs = smem;                  // x tile; reused as attention-output tile
    float* qs = xs + NTOK*STRIDE;
    float* ks = qs + NTOK*STRIDE;
    float* vs = ks + NTOK*STRIDE;
    float* at = vs + NTOK*STRIDE;      // 49 x 50 scores

    const int b   = blockIdx.x;
    const int tid = threadIdx.x;
    const float scale = 0.17677669529663687f;  // 32^-0.5

    // ---- load x tile (49 x 192) ----
    const float* xg = x + (size_t)b * (NTOK*DIM);
    for (int idx = tid; idx < NTOK*DIM; idx += 192)
        xs[(idx/DIM)*STRIDE + (idx%DIM)] = xg[idx];
    __syncthreads();

    // ---- QKV GEMM: 576 output columns, thread handles cols tid, tid+192, tid+384 ----
    #pragma unroll 1
    for (int rep = 0; rep < 3; rep++) {
        const int j = tid + rep*192;
        float acc[NTOK];
        #pragma unroll
        for (int i = 0; i < NTOK; i++) acc[i] = 0.f;

        const float4* wrow = (const float4*)(qkv_w + j*DIM);
        #pragma unroll 4
        for (int k4 = 0; k4 < DIM/4; k4++) {
            const float4 w4 = __ldg(wrow + k4);
            const int k = k4 * 4;
            #pragma unroll
            for (int i = 0; i < NTOK; i++) {
                const float* xr = xs + i*STRIDE + k;
                acc[i] += xr[0]*w4.x + xr[1]*w4.y + xr[2]*w4.z + xr[3]*w4.w;
            }
        }
        const float bj = __ldg(qkv_b + j);
        float* dst; int col; float mult = 1.f;
        if (j < DIM)        { dst = qs; col = j;         mult = scale; }
        else if (j < 2*DIM) { dst = ks; col = j - DIM;   }
        else                { dst = vs; col = j - 2*DIM; }
        #pragma unroll
        for (int i = 0; i < NTOK; i++) dst[i*STRIDE + col] = (acc[i] + bj) * mult;
    }
    __syncthreads();

    // ---- attention per head (scores -> softmax -> AV) ----
    const float* maskp = mask + (size_t)(b & (NWIN-1)) * (NTOK*NTOK);
    float* os = xs;   // x tile is dead; reuse as per-window attention output (49 x 192)
    const int w    = tid >> 5;
    const int lane = tid & 31;

    for (int h = 0; h < HEADS; h++) {
        const int hb = h * HD;

        // scores: attn[i][j] = q_i . k_j + bias + mask
        for (int e = tid; e < NTOK*NTOK; e += 192) {
            const int i = e / NTOK, j = e % NTOK;
            const float* qr = qs + i*STRIDE + hb;
            const float* kr = ks + j*STRIDE + hb;
            float s = 0.f;
            #pragma unroll
            for (int d = 0; d < HD; d++) s += qr[d] * kr[d];
            s += __ldg(bias_table + __ldg(rel_idx + e)*HEADS + h) + __ldg(maskp + e);
            at[i*ATS + j] = s;
        }
        __syncthreads();

        // softmax: one warp per row (6 warps, rows strided)
        for (int i = w; i < NTOK; i += 6) {
            float v1 = at[i*ATS + lane];
            float v2 = (lane + 32 < NTOK) ? at[i*ATS + lane + 32] : -3.4e38f;
            float m = fmaxf(v1, v2);
            #pragma unroll
            for (int o = 16; o > 0; o >>= 1)
                m = fmaxf(m, __shfl_xor_sync(0xffffffffu, m, o));
            float e1 = __expf(v1 - m);
            float e2 = (lane + 32 < NTOK) ? __expf(v2 - m) : 0.f;
            float s = e1 + e2;
            #pragma unroll
            for (int o = 16; o > 0; o >>= 1)
                s += __shfl_xor_sync(0xffffffffu, s, o);
            const float inv = __frcp_rn(s);
            at[i*ATS + lane] = e1 * inv;
            if (lane + 32 < NTOK) at[i*ATS + lane + 32] = e2 * inv;
        }
        __syncthreads();

        // AV: out[i][hb+d] = sum_j attn[i][j] * v[j][hb+d]
        for (int e = tid; e < NTOK*HD; e += 192) {
            const int i = e / HD, d = e % HD;
            const float* ar = at + i*ATS;
            const float* vr = vs + hb + d;
            float s = 0.f;
            #pragma unroll
            for (int j = 0; j < NTOK; j++) s += ar[j] * vr[j*STRIDE];
            os[i*STRIDE + hb + d] = s;
        }
        __syncthreads();
    }

    // ---- output projection: thread handles column c = tid (192 cols) ----
    {
        const int c = tid;
        float acc[NTOK];
        #pragma unroll
        for (int i = 0; i < NTOK; i++) acc[i] = 0.f;

        const float4* wrow = (const float4*)(proj_w + c*DIM);
        #pragma unroll 4
        for (int k4 = 0; k4 < DIM/4; k4++) {
            const float4 w4 = __ldg(wrow + k4);
            const int k = k4 * 4;
            #pragma unroll
            for (int i = 0; i < NTOK; i++) {
                const float* orow = os + i*STRIDE + k;
                acc[i] += orow[0]*w4.x + orow[1]*w4.y + orow[2]*w4.z + orow[3]*w4.w;
            }
        }
        const float bc = __ldg(proj_b + c);
        float* og = out + (size_t)b * (NTOK*DIM);
        #pragma unroll
        for (int i = 0; i < NTOK; i++) og[i*DIM + c] = acc[i] + bc;
    }
}

extern "C" void kernel_launch(void* const* d_in, const int* in_sizes, int n_in,
                              void* d_out, int out_size)
{
    const float* x          = (const float*)d_in[0];
    const float* mask       = (const float*)d_in[1];
    const float* qkv_w      = (const float*)d_in[2];
    const float* qkv_b      = (const float*)d_in[3];
    const float* proj_w     = (const float*)d_in[4];
    const float* proj_b     = (const float*)d_in[5];
    const float* bias_table = (const float*)d_in[6];
    const int*   rel_idx    = (const int*)d_in[7];
    float* out = (float*)d_out;

    const int smem_bytes = SMEM_FLOATS * (int)sizeof(float);
    cudaFuncSetAttribute(win_attn_kernel,
                         cudaFuncAttributeMaxDynamicSharedMemorySize, smem_bytes);

    win_attn_kernel<<<4096, 192, smem_bytes>>>(
        x, mask, qkv_w, qkv_b, proj_w, proj_b, bias_table, rel_idx, out);
}

// round 2
// speedup vs baseline: 3.4977x; 3.4977x over previous
#include <cuda_runtime.h>

#define DIM    192
#define HEADS  6
#define HD     32
#define NTOK   49
#define NWIN   64

#define SX     196      // row stride for 192-wide smem tiles (conflict-free frags)
#define PSTR   60       // P buffer row stride (conflict-free A-frag reads)

#define SM_XS  0
#define SM_QS  (64*SX)
#define SM_KS  (2*64*SX)
#define SM_VS  (2*64*SX + 56*SX)
#define SM_PB  (2*64*SX + 2*56*SX)
#define SM_TOT (2*64*SX + 2*56*SX + 6*16*PSTR)   // 52800 floats = 211,200 B

// ---- persistent scratch (built once per launch by prep kernel) ----
__device__ float g_Wt[192*576];        // qkv_w transposed (K-major), tf32-rounded
__device__ float g_Pt[192*192];        // proj_w transposed (K-major), tf32-rounded
__device__ float g_biasx[HEADS*NTOK*NTOK];  // bias gathered per head

__device__ __forceinline__ unsigned f2tf(float f) {
    unsigned r; asm("cvt.rna.tf32.f32 %0, %1;" : "=r"(r) : "f"(f)); return r;
}
__device__ __forceinline__ float tf32r(float f) { return __uint_as_float(f2tf(f)); }

__device__ __forceinline__ void mma_tf32(float d[4], const unsigned a[4], const unsigned b[2]) {
    asm volatile(
        "mma.sync.aligned.m16n8k8.row.col.f32.tf32.tf32.f32 "
        "{%0,%1,%2,%3}, {%4,%5,%6,%7}, {%8,%9}, {%0,%1,%2,%3};\n"
        : "+f"(d[0]), "+f"(d[1]), "+f"(d[2]), "+f"(d[3])
        : "r"(a[0]), "r"(a[1]), "r"(a[2]), "r"(a[3]), "r"(b[0]), "r"(b[1]));
}

// ---------------- prep kernel ----------------
__global__ void prep_kernel(const float* __restrict__ qkv_w,
                            const float* __restrict__ proj_w,
                            const float* __restrict__ bias_table,
                            const int*   __restrict__ rel_idx)
{
    const int NW_ = 192*576, NP_ = 192*192, NB_ = HEADS*NTOK*NTOK;
    for (int idx = blockIdx.x*blockDim.x + threadIdx.x;
         idx < NW_ + NP_ + NB_; idx += gridDim.x*blockDim.x) {
        if (idx < NW_) {
            int k = idx / 576, j = idx % 576;
            g_Wt[idx] = tf32r(qkv_w[j*192 + k]);
        } else if (idx < NW_ + NP_) {
            int t = idx - NW_;
            int k = t / 192, j = t % 192;
            g_Pt[t] = tf32r(proj_w[j*192 + k]);
        } else {
            int t = idx - NW_ - NP_;
            int h = t / (NTOK*NTOK), e = t % (NTOK*NTOK);
            g_biasx[t] = bias_table[rel_idx[e]*HEADS + h];
        }
    }
}

// GEMM chunk: A (m=64) from smem (stride SX, tf32-rounded), B from global K-major
template<int NT, int KS, int BLD>
__device__ __forceinline__ void gemm_chunk(const float* __restrict__ As,
                                           const float* __restrict__ Bg,
                                           int n_base, int g, int tig,
                                           float acc[4][NT][4])
{
    #pragma unroll
    for (int ks = 0; ks < KS; ks++) {
        const int k0 = ks*8;
        unsigned a[4][4];
        #pragma unroll
        for (int mt = 0; mt < 4; mt++) {
            const float* ap = As + (mt*16 + g)*SX + k0 + tig;
            a[mt][0] = __float_as_uint(ap[0]);
            a[mt][1] = __float_as_uint(ap[8*SX]);
            a[mt][2] = __float_as_uint(ap[4]);
            a[mt][3] = __float_as_uint(ap[8*SX + 4]);
        }
        #pragma unroll
        for (int nt = 0; nt < NT; nt++) {
            unsigned bb[2];
            const float* bp = Bg + (k0 + tig)*BLD + n_base + nt*8 + g;
            bb[0] = __float_as_uint(__ldg(bp));
            bb[1] = __float_as_uint(__ldg(bp + 4*BLD));
            #pragma unroll
            for (int mt = 0; mt < 4; mt++) mma_tf32(acc[mt][nt], a[mt], bb);
        }
    }
}

// ---------------- main kernel ----------------
__global__ __launch_bounds__(256, 1)
void win_attn_mma(const float* __restrict__ x,
                  const float* __restrict__ mask,
                  const float* __restrict__ qkv_b,
                  const float* __restrict__ proj_b,
                  float* __restrict__ out)
{
    extern __shared__ float sm[];
    float* xs = sm + SM_XS;   // 64 x SX; reused as attention-output tile
    float* qs = sm + SM_QS;   // 64 x SX
    float* ks = sm + SM_KS;   // 56 x SX
    float* vs = sm + SM_VS;   // 56 x SX
    float* Pb = sm + SM_PB;   // 6 warps x 16 x PSTR

    const int tid  = threadIdx.x;
    const int w    = tid >> 5;
    const int lane = tid & 31;
    const int g    = lane >> 2;   // groupID
    const int tig  = lane & 3;    // thread-in-group
    const int b    = blockIdx.x;
    const float scale = 0.17677669529663687f;  // 32^-0.5

    // zero-fill all smem (pad rows must be exactly zero / finite)
    for (int i = tid; i < SM_TOT; i += 256) sm[i] = 0.f;
    __syncthreads();

    // load x tile (49 x 192), tf32-rounded
    const float* xg = x + (size_t)b * (NTOK*DIM);
    for (int i = tid; i < NTOK*DIM; i += 256)
        xs[(i/DIM)*SX + (i%DIM)] = tf32r(xg[i]);
    __syncthreads();

    // ---- QKV GEMM: warp w owns cols [w*72, w*72+72), 3 chunks of 24 ----
    #pragma unroll 1
    for (int chunk = 0; chunk < 3; chunk++) {
        const int n_base = w*72 + chunk*24;
        float acc[4][3][4];
        #pragma unroll
        for (int mt = 0; mt < 4; mt++)
            #pragma unroll
            for (int nt = 0; nt < 3; nt++)
                #pragma unroll
                for (int e = 0; e < 4; e++) acc[mt][nt][e] = 0.f;

        gemm_chunk<3, 24, 576>(xs, g_Wt, n_base, g, tig, acc);

        #pragma unroll
        for (int nt = 0; nt < 3; nt++) {
            const int j0 = n_base + nt*8 + 2*tig;
            const float bj0 = __ldg(qkv_b + j0);
            const float bj1 = __ldg(qkv_b + j0 + 1);
            float* dst; int col0; float mult; bool isq;
            if (j0 < 192)      { dst = qs; col0 = j0;       mult = scale; isq = true; }
            else if (j0 < 384) { dst = ks; col0 = j0 - 192; mult = 1.f;   isq = false; }
            else               { dst = vs; col0 = j0 - 384; mult = 1.f;   isq = false; }
            #pragma unroll
            for (int mt = 0; mt < 4; mt++) {
                #pragma unroll
                for (int hf = 0; hf < 2; hf++) {
                    const int row = mt*16 + g + hf*8;
                    if (!isq && row >= 56) continue;   // k/v tiles have 56 rows
                    float v0 = (acc[mt][nt][hf*2+0] + bj0) * mult;
                    float v1 = (acc[mt][nt][hf*2+1] + bj1) * mult;
                    float2* p = (float2*)(dst + row*SX + col0);
                    *p = make_float2(tf32r(v0), tf32r(v1));
                }
            }
        }
    }
    __syncthreads();

    // ---- attention: warp w = head w (warps 6,7 idle) ----
    if (w < HEADS) {
        const int hb = w * HD;
        const float* maskp = mask + (size_t)(b & (NWIN-1)) * (NTOK*NTOK);
        const float* biasp = g_biasx + w * (NTOK*NTOK);

        // scores QK^T: M=64 (4 mt), N=56 (7 nt), K=32 (4 ksteps)
        float sc[4][7][4];
        #pragma unroll
        for (int mt = 0; mt < 4; mt++)
            #pragma unroll
            for (int nt = 0; nt < 7; nt++)
                #pragma unroll
                for (int e = 0; e < 4; e++) sc[mt][nt][e] = 0.f;

        #pragma unroll
        for (int kk = 0; kk < 4; kk++) {
            const int k0 = kk*8;
            unsigned a[4][4];
            #pragma unroll
            for (int mt = 0; mt < 4; mt++) {
                const float* ap = qs + (mt*16 + g)*SX + hb + k0 + tig;
                a[mt][0] = __float_as_uint(ap[0]);
                a[mt][1] = __float_as_uint(ap[8*SX]);
                a[mt][2] = __float_as_uint(ap[4]);
                a[mt][3] = __float_as_uint(ap[8*SX + 4]);
            }
            #pragma unroll
            for (int nt = 0; nt < 7; nt++) {
                unsigned bb[2];
                const float* bp = ks + (nt*8 + g)*SX + hb + k0 + tig;
                bb[0] = __float_as_uint(bp[0]);
                bb[1] = __float_as_uint(bp[4]);
                #pragma unroll
                for (int mt = 0; mt < 4; mt++) mma_tf32(sc[mt][nt], a[mt], bb);
            }
        }

        // add bias + mask, pad -> -1e30
        #pragma unroll
        for (int mt = 0; mt < 4; mt++)
            #pragma unroll
            for (int nt = 0; nt < 7; nt++)
                #pragma unroll
                for (int e = 0; e < 4; e++) {
                    const int i = mt*16 + g + (e >> 1)*8;
                    const int j = nt*8 + 2*tig + (e & 1);
                    if (i < NTOK && j < NTOK)
                        sc[mt][nt][e] += __ldg(biasp + i*NTOK + j) + __ldg(maskp + i*NTOK + j);
                    else
                        sc[mt][nt][e] = -1e30f;
                }

        // in-register softmax: row i owned by the 4 lanes of a quad
        #pragma unroll
        for (int mt = 0; mt < 4; mt++) {
            #pragma unroll
            for (int hf = 0; hf < 2; hf++) {
                float m = -1e30f;
                #pragma unroll
                for (int nt = 0; nt < 7; nt++) {
                    m = fmaxf(m, sc[mt][nt][hf*2+0]);
                    m = fmaxf(m, sc[mt][nt][hf*2+1]);
                }
                m = fmaxf(m, __shfl_xor_sync(0xffffffffu, m, 1));
                m = fmaxf(m, __shfl_xor_sync(0xffffffffu, m, 2));
                float s = 0.f;
                #pragma unroll
                for (int nt = 0; nt < 7; nt++) {
                    float e0 = __expf(sc[mt][nt][hf*2+0] - m);
                    float e1 = __expf(sc[mt][nt][hf*2+1] - m);
                    sc[mt][nt][hf*2+0] = e0;
                    sc[mt][nt][hf*2+1] = e1;
                    s += e0 + e1;
                }
                s += __shfl_xor_sync(0xffffffffu, s, 1);
                s += __shfl_xor_sync(0xffffffffu, s, 2);
                const float inv = __frcp_rn(s);
                #pragma unroll
                for (int nt = 0; nt < 7; nt++) {
                    sc[mt][nt][hf*2+0] *= inv;
                    sc[mt][nt][hf*2+1] *= inv;
                }
            }
        }

        // AV per m-tile: P -> smem (A layout source), mma with V
        float* Pw = Pb + w * 16 * PSTR;
        #pragma unroll 1
        for (int mt = 0; mt < 4; mt++) {
            #pragma unroll
            for (int nt = 0; nt < 7; nt++) {
                const int c0 = nt*8 + 2*tig;
                *(float2*)(Pw + g*PSTR + c0) =
                    make_float2(tf32r(sc[mt][nt][0]), tf32r(sc[mt][nt][1]));
                *(float2*)(Pw + (g+8)*PSTR + c0) =
                    make_float2(tf32r(sc[mt][nt][2]), tf32r(sc[mt][nt][3]));
            }
            __syncwarp();

            float o[4][4];
            #pragma unroll
            for (int nv = 0; nv < 4; nv++)
                #pragma unroll
                for (int e = 0; e < 4; e++) o[nv][e] = 0.f;

            #pragma unroll
            for (int kk = 0; kk < 7; kk++) {
                const int k0 = kk*8;
                unsigned a[4];
                const float* ap = Pw + g*PSTR + k0 + tig;
                a[0] = __float_as_uint(ap[0]);
                a[1] = __float_as_uint(ap[8*PSTR]);
                a[2] = __float_as_uint(ap[4]);
                a[3] = __float_as_uint(ap[8*PSTR + 4]);
                #pragma unroll
                for (int nv = 0; nv < 4; nv++) {
                    unsigned bb[2];
                    const float* bp = vs + (k0 + tig)*SX + hb + nv*8 + g;
                    bb[0] = __float_as_uint(bp[0]);
                    bb[1] = __float_as_uint(bp[4*SX]);
                    mma_tf32(o[nv], a, bb);
                }
            }

            #pragma unroll
            for (int nv = 0; nv < 4; nv++) {
                const int c0 = hb + nv*8 + 2*tig;
                const int r0 = mt*16 + g;
                *(float2*)(xs + r0*SX + c0)     = make_float2(tf32r(o[nv][0]), tf32r(o[nv][1]));
                *(float2*)(xs + (r0+8)*SX + c0) = make_float2(tf32r(o[nv][2]), tf32r(o[nv][3]));
            }
            __syncwarp();
        }
    }
    __syncthreads();

    // ---- output projection: warp w owns cols [w*24, w*24+24) ----
    {
        const int n_base = w * 24;
        float acc[4][3][4];
        #pragma unroll
        for (int mt = 0; mt < 4; mt++)
            #pragma unroll
            for (int nt = 0; nt < 3; nt++)
                #pragma unroll
                for (int e = 0; e < 4; e++) acc[mt][nt][e] = 0.f;

        gemm_chunk<3, 24, 192>(xs, g_Pt, n_base, g, tig, acc);

        float* og = out + (size_t)b * (NTOK*DIM);
        #pragma unroll
        for (int nt = 0; nt < 3; nt++) {
            const int j0 = n_base + nt*8 + 2*tig;
            const float pb0 = __ldg(proj_b + j0);
            const float pb1 = __ldg(proj_b + j0 + 1);
            #pragma unroll
            for (int mt = 0; mt < 4; mt++) {
                #pragma unroll
                for (int hf = 0; hf < 2; hf++) {
                    const int row = mt*16 + g + hf*8;
                    if (row < NTOK) {
                        *(float2*)(og + row*DIM + j0) =
                            make_float2(acc[mt][nt][hf*2+0] + pb0,
                                        acc[mt][nt][hf*2+1] + pb1);
                    }
                }
            }
        }
    }
}

extern "C" void kernel_launch(void* const* d_in, const int* in_sizes, int n_in,
                              void* d_out, int out_size)
{
    const float* x          = (const float*)d_in[0];
    const float* mask       = (const float*)d_in[1];
    const float* qkv_w      = (const float*)d_in[2];
    const float* qkv_b      = (const float*)d_in[3];
    const float* proj_w     = (const float*)d_in[4];
    const float* proj_b     = (const float*)d_in[5];
    const float* bias_table = (const float*)d_in[6];
    const int*   rel_idx    = (const int*)d_in[7];
    float* out = (float*)d_out;

    prep_kernel<<<256, 256>>>(qkv_w, proj_w, bias_table, rel_idx);

    const int smem_bytes = SM_TOT * (int)sizeof(float);
    cudaFuncSetAttribute(win_attn_mma,
                         cudaFuncAttributeMaxDynamicSharedMemorySize, smem_bytes);
    win_attn_mma<<<4096, 256, smem_bytes>>>(x, mask, qkv_b, proj_b, out);
}

// round 3
// speedup vs baseline: 4.0360x; 1.1539x over previous
#include <cuda_runtime.h>

#define DIM    192
#define HEADS  6
#define HD     32
#define NTOK   49
#define NWIN   64
#define BMS    50     // bias+mask row stride (even -> aligned float2)

// packed smem sizes (floats)
#define XS_F   12288          // A_pack 64x192  (24 kstep x 4 mt x 32 lane x 4)
#define KS_F   10752          // B_pack 56x192  (24 kstep x 7 nt x 32 lane x 2)
#define VS_F   10752          // V_pack 56x192  (7 kk x 24 cblk x 32 lane x 2)
#define PW_F   896            // per-warp P pack (7 kk x 32 lane x 4)
#define SM_F   (2*XS_F + KS_F + VS_F + 6*PW_F)   // 51456 floats = 205,824 B

// ---- persistent scratch (filled by prep kernel every launch) ----
__device__ float g_Wt[24*72*32*2];            // qkv_w fragment-packed
__device__ float g_Pt[24*24*32*2];            // proj_w fragment-packed
__device__ float g_bm[NWIN*HEADS*NTOK*BMS];   // bias+mask combined

__device__ __forceinline__ float tf32r(float f) {
    unsigned r; asm("cvt.rna.tf32.f32 %0, %1;" : "=r"(r) : "f"(f));
    return __uint_as_float(r);
}

__device__ __forceinline__ void mma4(float d[4], float4 a, float2 b) {
    asm volatile(
        "mma.sync.aligned.m16n8k8.row.col.f32.tf32.tf32.f32 "
        "{%0,%1,%2,%3}, {%4,%5,%6,%7}, {%8,%9}, {%0,%1,%2,%3};\n"
        : "+f"(d[0]), "+f"(d[1]), "+f"(d[2]), "+f"(d[3])
        : "r"(__float_as_uint(a.x)), "r"(__float_as_uint(a.y)),
          "r"(__float_as_uint(a.z)), "r"(__float_as_uint(a.w)),
          "r"(__float_as_uint(b.x)), "r"(__float_as_uint(b.y)));
}

// slot maps (float indices within the packed tiles)
__device__ __forceinline__ int slotA(int row, int col) {
    return (((col >> 3) * 4 + (row >> 4)) * 32 + ((row & 7) * 4 + (col & 3))) * 4
           + ((col >> 2) & 1) * 2 + ((row >> 3) & 1);
}
__device__ __forceinline__ int slotK(int n, int col) {
    return (((col >> 3) * 7 + (n >> 3)) * 32 + ((n & 7) * 4 + (col & 3))) * 2
           + ((col >> 2) & 1);
}
__device__ __forceinline__ int slotV(int r, int c) {
    return (((r >> 3) * 24 + (c >> 3)) * 32 + ((c & 7) * 4 + (r & 3))) * 2
           + ((r >> 2) & 1);
}
__device__ __forceinline__ int slotP(int prow, int pcol) {
    return ((pcol >> 3) * 32 + ((prow & 7) * 4 + (pcol & 3))) * 4
           + ((pcol >> 2) & 1) * 2 + ((prow >> 3) & 1);
}

// ---------------- prep kernel ----------------
__global__ void prep_kernel(const float* __restrict__ qkv_w,
                            const float* __restrict__ proj_w,
                            const float* __restrict__ bias_table,
                            const int*   __restrict__ rel_idx,
                            const float* __restrict__ mask)
{
    const int NWE = 192*576, NPE = 192*192, NBE = NWIN*HEADS*NTOK*NTOK;
    for (int idx = blockIdx.x*blockDim.x + threadIdx.x;
         idx < NWE + NPE + NBE; idx += gridDim.x*blockDim.x) {
        if (idx < NWE) {
            int k = idx / 576, n = idx % 576;
            int s = (((k >> 3) * 72 + (n >> 3)) * 32 + ((n & 7) * 4 + (k & 3))) * 2
                    + ((k >> 2) & 1);
            g_Wt[s] = tf32r(qkv_w[n*192 + k]);
        } else if (idx < NWE + NPE) {
            int t = idx - NWE;
            int k = t / 192, n = t % 192;
            int s = (((k >> 3) * 24 + (n >> 3)) * 32 + ((n & 7) * 4 + (k & 3))) * 2
                    + ((k >> 2) & 1);
            g_Pt[s] = tf32r(proj_w[n*192 + k]);
        } else {
            int t = idx - NWE - NPE;
            int win = t / (HEADS*NTOK*NTOK);
            int r   = t % (HEADS*NTOK*NTOK);
            int h = r / (NTOK*NTOK);
            int e = r % (NTOK*NTOK);
            int i = e / NTOK, j = e % NTOK;
            g_bm[((win*HEADS + h)*NTOK + i)*BMS + j] =
                bias_table[rel_idx[e]*HEADS + h] + mask[win*(NTOK*NTOK) + e];
        }
    }
}

// ---------------- main kernel ----------------
__global__ __launch_bounds__(256, 1)
void win_attn3(const float* __restrict__ x,
               const float* __restrict__ qkv_b,
               const float* __restrict__ proj_b,
               float* __restrict__ out)
{
    extern __shared__ float sm[];
    float* xs = sm;                    // A_pack of x; reused as attn-out A_pack
    float* qs = xs + XS_F;             // A_pack of Q (scaled)
    float* ks = qs + XS_F;             // B_pack of K
    float* vs = ks + KS_F;             // V_pack
    float* Pb = vs + VS_F;             // 6 x PW_F

    const int tid  = threadIdx.x;
    const int w    = tid >> 5;
    const int lane = tid & 31;
    const int g    = lane >> 2;
    const int tig  = lane & 3;
    const int b    = blockIdx.x;
    const float scale = 0.17677669529663687f;

    // zero xs (pad rows 49..63 must be 0)
    for (int i = tid; i < XS_F; i += 256) xs[i] = 0.f;
    __syncthreads();

    // scatter x into A_pack, tf32-rounded
    const float* xg = x + (size_t)b * (NTOK*DIM);
    for (int i = tid; i < NTOK*DIM; i += 256) {
        int row = i / DIM, col = i % DIM;
        xs[slotA(row, col)] = tf32r(xg[i]);
    }
    __syncthreads();

    // ---- QKV GEMM: warp owns 72 cols (9 nt), single pass ----
    {
        const int wnb = w * 9;   // n-block base
        float acc[4][9][4];
        #pragma unroll
        for (int mt = 0; mt < 4; mt++)
            #pragma unroll
            for (int nt = 0; nt < 9; nt++)
                #pragma unroll
                for (int e = 0; e < 4; e++) acc[mt][nt][e] = 0.f;

        const float4* Af = (const float4*)xs;
        const float2* Wf = (const float2*)g_Wt;
        #pragma unroll 4
        for (int kk = 0; kk < 24; kk++) {
            float4 a4[4];
            #pragma unroll
            for (int mt = 0; mt < 4; mt++) a4[mt] = Af[(kk*4 + mt)*32 + lane];
            #pragma unroll
            for (int nt = 0; nt < 9; nt++) {
                float2 b2 = __ldg(Wf + (kk*72 + wnb + nt)*32 + lane);
                #pragma unroll
                for (int mt = 0; mt < 4; mt++) mma4(acc[mt][nt], a4[mt], b2);
            }
        }

        #pragma unroll
        for (int nt = 0; nt < 9; nt++) {
            const int j0 = (wnb + nt)*8 + 2*tig;
            const float bj0 = __ldg(qkv_b + j0);
            const float bj1 = __ldg(qkv_b + j0 + 1);
            #pragma unroll
            for (int mt = 0; mt < 4; mt++) {
                #pragma unroll
                for (int hf = 0; hf < 2; hf++) {
                    const int row = mt*16 + g + hf*8;
                    float v0 = acc[mt][nt][hf*2+0] + bj0;
                    float v1 = acc[mt][nt][hf*2+1] + bj1;
                    if (j0 < 192) {
                        qs[slotA(row, j0)]     = tf32r(v0 * scale);
                        qs[slotA(row, j0 + 1)] = tf32r(v1 * scale);
                    } else if (j0 < 384) {
                        if (row < 56) {
                            ks[slotK(row, j0 - 192)]     = tf32r(v0);
                            ks[slotK(row, j0 - 192 + 1)] = tf32r(v1);
                        }
                    } else {
                        if (row < 56) {
                            vs[slotV(row, j0 - 384)]     = tf32r(v0);
                            vs[slotV(row, j0 - 384 + 1)] = tf32r(v1);
                        }
                    }
                }
            }
        }
    }
    __syncthreads();

    // ---- attention: warp w = head w (warps 6,7 idle) ----
    if (w < HEADS) {
        const int hb = w * HD;
        const int kb = w * 4;   // global kstep base for this head

        float sc[4][7][4];
        #pragma unroll
        for (int mt = 0; mt < 4; mt++)
            #pragma unroll
            for (int nt = 0; nt < 7; nt++)
                #pragma unroll
                for (int e = 0; e < 4; e++) sc[mt][nt][e] = 0.f;

        const float4* Aq = (const float4*)qs;
        const float2* Kf = (const float2*)ks;
        #pragma unroll
        for (int kk = 0; kk < 4; kk++) {
            float4 a4[4];
            #pragma unroll
            for (int mt = 0; mt < 4; mt++) a4[mt] = Aq[((kb+kk)*4 + mt)*32 + lane];
            #pragma unroll
            for (int nt = 0; nt < 7; nt++) {
                float2 b2 = Kf[((kb+kk)*7 + nt)*32 + lane];
                #pragma unroll
                for (int mt = 0; mt < 4; mt++) mma4(sc[mt][nt], a4[mt], b2);
            }
        }

        // bias+mask (combined table), pad -> -1e30
        const float2* bmp = (const float2*)(g_bm
                          + (size_t)((b & (NWIN-1))*HEADS + w) * NTOK * BMS);
        #pragma unroll
        for (int mt = 0; mt < 4; mt++) {
            const int i0 = mt*16 + g;
            #pragma unroll
            for (int nt = 0; nt < 7; nt++) {
                const int j0 = nt*8 + 2*tig;
                float2 u0 = make_float2(0.f, 0.f), u1 = u0;
                if (i0 < NTOK && j0 < NTOK)     u0 = __ldg(bmp + (i0*BMS + j0)/2);
                if (i0+8 < NTOK && j0 < NTOK)   u1 = __ldg(bmp + ((i0+8)*BMS + j0)/2);
                sc[mt][nt][0] = (i0   < NTOK && j0   < NTOK) ? sc[mt][nt][0] + u0.x : -1e30f;
                sc[mt][nt][1] = (i0   < NTOK && j0+1 < NTOK) ? sc[mt][nt][1] + u0.y : -1e30f;
                sc[mt][nt][2] = (i0+8 < NTOK && j0   < NTOK) ? sc[mt][nt][2] + u1.x : -1e30f;
                sc[mt][nt][3] = (i0+8 < NTOK && j0+1 < NTOK) ? sc[mt][nt][3] + u1.y : -1e30f;
            }
        }

        // in-register softmax (row owned by a quad)
        #pragma unroll
        for (int mt = 0; mt < 4; mt++) {
            #pragma unroll
            for (int hf = 0; hf < 2; hf++) {
                float m = -1e30f;
                #pragma unroll
                for (int nt = 0; nt < 7; nt++) {
                    m = fmaxf(m, sc[mt][nt][hf*2+0]);
                    m = fmaxf(m, sc[mt][nt][hf*2+1]);
                }
                m = fmaxf(m, __shfl_xor_sync(0xffffffffu, m, 1));
                m = fmaxf(m, __shfl_xor_sync(0xffffffffu, m, 2));
                float s = 0.f;
                #pragma unroll
                for (int nt = 0; nt < 7; nt++) {
                    float e0 = __expf(sc[mt][nt][hf*2+0] - m);
                    float e1 = __expf(sc[mt][nt][hf*2+1] - m);
                    sc[mt][nt][hf*2+0] = e0;
                    sc[mt][nt][hf*2+1] = e1;
                    s += e0 + e1;
                }
                s += __shfl_xor_sync(0xffffffffu, s, 1);
                s += __shfl_xor_sync(0xffffffffu, s, 2);
                const float inv = __frcp_rn(s);
                #pragma unroll
                for (int nt = 0; nt < 7; nt++) {
                    sc[mt][nt][hf*2+0] *= inv;
                    sc[mt][nt][hf*2+1] *= inv;
                }
            }
        }

        // AV per m-tile
        float* Pw = Pb + w * PW_F;
        const float4* Pf = (const float4*)Pw;
        const float2* Vf = (const float2*)vs;
        #pragma unroll 1
        for (int mt = 0; mt < 4; mt++) {
            #pragma unroll
            for (int nt = 0; nt < 7; nt++) {
                const int pc = nt*8 + 2*tig;
                Pw[slotP(g,     pc)]     = tf32r(sc[mt][nt][0]);
                Pw[slotP(g,     pc + 1)] = tf32r(sc[mt][nt][1]);
                Pw[slotP(g + 8, pc)]     = tf32r(sc[mt][nt][2]);
                Pw[slotP(g + 8, pc + 1)] = tf32r(sc[mt][nt][3]);
            }
            __syncwarp();

            float o[4][4];
            #pragma unroll
            for (int nv = 0; nv < 4; nv++)
                #pragma unroll
                for (int e = 0; e < 4; e++) o[nv][e] = 0.f;

            #pragma unroll
            for (int kk = 0; kk < 7; kk++) {
                float4 a4 = Pf[kk*32 + lane];
                #pragma unroll
                for (int nv = 0; nv < 4; nv++) {
                    float2 b2 = Vf[(kk*24 + (hb >> 3) + nv)*32 + lane];
                    mma4(o[nv], a4, b2);
                }
            }

            #pragma unroll
            for (int nv = 0; nv < 4; nv++) {
                const int c0 = hb + nv*8 + 2*tig;
                const int r0 = mt*16 + g;
                xs[slotA(r0,     c0)]     = tf32r(o[nv][0]);
                xs[slotA(r0,     c0 + 1)] = tf32r(o[nv][1]);
                xs[slotA(r0 + 8, c0)]     = tf32r(o[nv][2]);
                xs[slotA(r0 + 8, c0 + 1)] = tf32r(o[nv][3]);
            }
            __syncwarp();
        }
    }
    __syncthreads();

    // ---- output projection: warp owns 24 cols (3 nt) ----
    {
        float acc[4][3][4];
        #pragma unroll
        for (int mt = 0; mt < 4; mt++)
            #pragma unroll
            for (int nt = 0; nt < 3; nt++)
                #pragma unroll
                for (int e = 0; e < 4; e++) acc[mt][nt][e] = 0.f;

        const float4* Af = (const float4*)xs;
        const float2* Pf = (const float2*)g_Pt;
        #pragma unroll 4
        for (int kk = 0; kk < 24; kk++) {
            float4 a4[4];
            #pragma unroll
            for (int mt = 0; mt < 4; mt++) a4[mt] = Af[(kk*4 + mt)*32 + lane];
            #pragma unroll
            for (int nt = 0; nt < 3; nt++) {
                float2 b2 = __ldg(Pf + (kk*24 + w*3 + nt)*32 + lane);
                #pragma unroll
                for (int mt = 0; mt < 4; mt++) mma4(acc[mt][nt], a4[mt], b2);
            }
        }

        float* og = out + (size_t)b * (NTOK*DIM);
        #pragma unroll
        for (int nt = 0; nt < 3; nt++) {
            const int j0 = w*24 + nt*8 + 2*tig;
            const float pb0 = __ldg(proj_b + j0);
            const float pb1 = __ldg(proj_b + j0 + 1);
            #pragma unroll
            for (int mt = 0; mt < 4; mt++) {
                #pragma unroll
                for (int hf = 0; hf < 2; hf++) {
                    const int row = mt*16 + g + hf*8;
                    if (row < NTOK) {
                        *(float2*)(og + row*DIM + j0) =
                            make_float2(acc[mt][nt][hf*2+0] + pb0,
                                        acc[mt][nt][hf*2+1] + pb1);
                    }
                }
            }
        }
    }
}

extern "C" void kernel_launch(void* const* d_in, const int* in_sizes, int n_in,
                              void* d_out, int out_size)
{
    const float* x          = (const float*)d_in[0];
    const float* mask       = (const float*)d_in[1];
    const float* qkv_w      = (const float*)d_in[2];
    const float* qkv_b      = (const float*)d_in[3];
    const float* proj_w     = (const float*)d_in[4];
    const float* proj_b     = (const float*)d_in[5];
    const float* bias_table = (const float*)d_in[6];
    const int*   rel_idx    = (const int*)d_in[7];
    float* out = (float*)d_out;

    prep_kernel<<<1024, 256>>>(qkv_w, proj_w, bias_table, rel_idx, mask);

    const int smem_bytes = SM_F * (int)sizeof(float);
    cudaFuncSetAttribute(win_attn3,
                         cudaFuncAttributeMaxDynamicSharedMemorySize, smem_bytes);
    win_attn3<<<4096, 256, smem_bytes>>>(x, qkv_b, proj_b, out);
}

// round 4
// speedup vs baseline: 5.1997x; 1.2883x over previous
#include <cuda_runtime.h>

#define DIM    192
#define HEADS  6
#define HD     32
#define NTOK   49
#define NWIN   64
#define BMS    50
#define NTHR   384     // 12 warps

// packed smem sizes (floats)
#define XS_F   12288          // A_pack 64x192
#define KS_F   10752          // B_pack 56x192
#define VS_F   10752          // V_pack 56x192
#define PW_F   896            // per-warp P pack (7 kk x 32 lane x 4)
#define SM_F   (2*XS_F + KS_F + VS_F + 12*PW_F)   // 56832 floats = 227,328 B

__device__ float g_Wt[24*72*32*2];            // qkv_w fragment-packed
__device__ float g_Pt[24*24*32*2];            // proj_w fragment-packed
__device__ float g_bm[NWIN*HEADS*NTOK*BMS];   // bias+mask combined

__device__ __forceinline__ float tf32r(float f) {
    unsigned r; asm("cvt.rna.tf32.f32 %0, %1;" : "=r"(r) : "f"(f));
    return __uint_as_float(r);
}

__device__ __forceinline__ void mma4(float d[4], float4 a, float2 b) {
    asm volatile(
        "mma.sync.aligned.m16n8k8.row.col.f32.tf32.tf32.f32 "
        "{%0,%1,%2,%3}, {%4,%5,%6,%7}, {%8,%9}, {%0,%1,%2,%3};\n"
        : "+f"(d[0]), "+f"(d[1]), "+f"(d[2]), "+f"(d[3])
        : "r"(__float_as_uint(a.x)), "r"(__float_as_uint(a.y)),
          "r"(__float_as_uint(a.z)), "r"(__float_as_uint(a.w)),
          "r"(__float_as_uint(b.x)), "r"(__float_as_uint(b.y)));
}

__device__ __forceinline__ int slotA(int row, int col) {
    return (((col >> 3) * 4 + (row >> 4)) * 32 + ((row & 7) * 4 + (col & 3))) * 4
           + ((col >> 2) & 1) * 2 + ((row >> 3) & 1);
}
__device__ __forceinline__ int slotK(int n, int col) {
    return (((col >> 3) * 7 + (n >> 3)) * 32 + ((n & 7) * 4 + (col & 3))) * 2
           + ((col >> 2) & 1);
}
__device__ __forceinline__ int slotV(int r, int c) {
    return (((r >> 3) * 24 + (c >> 3)) * 32 + ((c & 7) * 4 + (r & 3))) * 2
           + ((r >> 2) & 1);
}
__device__ __forceinline__ int slotP(int prow, int pcol) {
    return ((pcol >> 3) * 32 + ((prow & 7) * 4 + (pcol & 3))) * 4
           + ((pcol >> 2) & 1) * 2 + ((prow >> 3) & 1);
}

// ---------------- prep kernel ----------------
__global__ void prep_kernel(const float* __restrict__ qkv_w,
                            const float* __restrict__ proj_w,
                            const float* __restrict__ bias_table,
                            const int*   __restrict__ rel_idx,
                            const float* __restrict__ mask)
{
    const int NWE = 192*576, NPE = 192*192, NBE = NWIN*HEADS*NTOK*NTOK;
    for (int idx = blockIdx.x*blockDim.x + threadIdx.x;
         idx < NWE + NPE + NBE; idx += gridDim.x*blockDim.x) {
        if (idx < NWE) {
            int k = idx / 576, n = idx % 576;
            int s = (((k >> 3) * 72 + (n >> 3)) * 32 + ((n & 7) * 4 + (k & 3))) * 2
                    + ((k >> 2) & 1);
            g_Wt[s] = tf32r(qkv_w[n*192 + k]);
        } else if (idx < NWE + NPE) {
            int t = idx - NWE;
            int k = t / 192, n = t % 192;
            int s = (((k >> 3) * 24 + (n >> 3)) * 32 + ((n & 7) * 4 + (k & 3))) * 2
                    + ((k >> 2) & 1);
            g_Pt[s] = tf32r(proj_w[n*192 + k]);
        } else {
            int t = idx - NWE - NPE;
            int win = t / (HEADS*NTOK*NTOK);
            int r   = t % (HEADS*NTOK*NTOK);
            int h = r / (NTOK*NTOK);
            int e = r % (NTOK*NTOK);
            int i = e / NTOK, j = e % NTOK;
            g_bm[((win*HEADS + h)*NTOK + i)*BMS + j] =
                bias_table[rel_idx[e]*HEADS + h] + mask[win*(NTOK*NTOK) + e];
        }
    }
}

// ---------------- main kernel ----------------
__global__ __launch_bounds__(NTHR, 1)
void win_attn4(const float* __restrict__ x,
               const float* __restrict__ qkv_b,
               const float* __restrict__ proj_b,
               float* __restrict__ out)
{
    extern __shared__ float sm[];
    float* xs = sm;                    // A_pack of x; reused as attn-out A_pack
    float* qs = xs + XS_F;             // A_pack of Q (scaled)
    float* ks = qs + XS_F;             // B_pack of K
    float* vs = ks + KS_F;             // V_pack
    float* Pb = vs + VS_F;             // 12 x PW_F

    const int tid  = threadIdx.x;
    const int w    = tid >> 5;
    const int lane = tid & 31;
    const int g    = lane >> 2;
    const int tig  = lane & 3;
    const int b    = blockIdx.x;
    const float scale = 0.17677669529663687f;

    // zero xs (pad rows must be 0 for x)
    for (int i = tid; i < XS_F; i += NTHR) xs[i] = 0.f;
    __syncthreads();

    // scatter x into A_pack, tf32-rounded
    const float* xg = x + (size_t)b * (NTOK*DIM);
    for (int i = tid; i < NTOK*DIM; i += NTHR) {
        int row = i / DIM, col = i % DIM;
        xs[slotA(row, col)] = tf32r(xg[i]);
    }
    __syncthreads();

    // ---- QKV GEMM: warp owns 48 cols (6 nt), single pass ----
    {
        const int wnb = w * 6;
        float acc[4][6][4];
        #pragma unroll
        for (int mt = 0; mt < 4; mt++)
            #pragma unroll
            for (int nt = 0; nt < 6; nt++)
                #pragma unroll
                for (int e = 0; e < 4; e++) acc[mt][nt][e] = 0.f;

        const float4* Af = (const float4*)xs;
        const float2* Wf = (const float2*)g_Wt;
        #pragma unroll 4
        for (int kk = 0; kk < 24; kk++) {
            float4 a4[4];
            #pragma unroll
            for (int mt = 0; mt < 4; mt++) a4[mt] = Af[(kk*4 + mt)*32 + lane];
            #pragma unroll
            for (int nt = 0; nt < 6; nt++) {
                float2 b2 = __ldg(Wf + (kk*72 + wnb + nt)*32 + lane);
                #pragma unroll
                for (int mt = 0; mt < 4; mt++) mma4(acc[mt][nt], a4[mt], b2);
            }
        }

        #pragma unroll
        for (int nt = 0; nt < 6; nt++) {
            const int j0 = (wnb + nt)*8 + 2*tig;
            const float bj0 = __ldg(qkv_b + j0);
            const float bj1 = __ldg(qkv_b + j0 + 1);
            #pragma unroll
            for (int mt = 0; mt < 4; mt++) {
                #pragma unroll
                for (int hf = 0; hf < 2; hf++) {
                    const int row = mt*16 + g + hf*8;
                    float v0 = acc[mt][nt][hf*2+0] + bj0;
                    float v1 = acc[mt][nt][hf*2+1] + bj1;
                    if (j0 < 192) {
                        qs[slotA(row, j0)]     = tf32r(v0 * scale);
                        qs[slotA(row, j0 + 1)] = tf32r(v1 * scale);
                    } else if (j0 < 384) {
                        if (row < 56) {
                            ks[slotK(row, j0 - 192)]     = tf32r(v0);
                            ks[slotK(row, j0 - 192 + 1)] = tf32r(v1);
                        }
                    } else {
                        if (row < 56) {
                            vs[slotV(row, j0 - 384)]     = tf32r(v0);
                            vs[slotV(row, j0 - 384 + 1)] = tf32r(v1);
                        }
                    }
                }
            }
        }
    }
    __syncthreads();

    // ---- attention: warp = (head h, M-half) : all 12 warps active ----
    {
        const int h    = w >> 1;
        const int half = w & 1;
        const int hb   = h * HD;
        const int kb   = h * 4;     // kstep base of this head's Q cols

        float sc[2][7][4];
        #pragma unroll
        for (int mt = 0; mt < 2; mt++)
            #pragma unroll
            for (int nt = 0; nt < 7; nt++)
                #pragma unroll
                for (int e = 0; e < 4; e++) sc[mt][nt][e] = 0.f;

        const float4* Aq = (const float4*)qs;
        const float2* Kf = (const float2*)ks;
        #pragma unroll
        for (int kk = 0; kk < 4; kk++) {
            float4 a4[2];
            #pragma unroll
            for (int mt = 0; mt < 2; mt++)
                a4[mt] = Aq[((kb+kk)*4 + half*2 + mt)*32 + lane];
            #pragma unroll
            for (int nt = 0; nt < 7; nt++) {
                float2 b2 = Kf[((kb+kk)*7 + nt)*32 + lane];
                #pragma unroll
                for (int mt = 0; mt < 2; mt++) mma4(sc[mt][nt], a4[mt], b2);
            }
        }

        // bias+mask, pad -> -1e30
        const float2* bmp = (const float2*)(g_bm
                          + (size_t)((b & (NWIN-1))*HEADS + h) * NTOK * BMS);
        #pragma unroll
        for (int mt = 0; mt < 2; mt++) {
            const int i0 = (half*2 + mt)*16 + g;
            #pragma unroll
            for (int nt = 0; nt < 7; nt++) {
                const int j0 = nt*8 + 2*tig;
                float2 u0 = make_float2(0.f, 0.f), u1 = u0;
                if (i0 < NTOK && j0 < NTOK)     u0 = __ldg(bmp + (i0*BMS + j0)/2);
                if (i0+8 < NTOK && j0 < NTOK)   u1 = __ldg(bmp + ((i0+8)*BMS + j0)/2);
                sc[mt][nt][0] = (i0   < NTOK && j0   < NTOK) ? sc[mt][nt][0] + u0.x : -1e30f;
                sc[mt][nt][1] = (i0   < NTOK && j0+1 < NTOK) ? sc[mt][nt][1] + u0.y : -1e30f;
                sc[mt][nt][2] = (i0+8 < NTOK && j0   < NTOK) ? sc[mt][nt][2] + u1.x : -1e30f;
                sc[mt][nt][3] = (i0+8 < NTOK && j0+1 < NTOK) ? sc[mt][nt][3] + u1.y : -1e30f;
            }
        }

        // in-register softmax
        #pragma unroll
        for (int mt = 0; mt < 2; mt++) {
            #pragma unroll
            for (int hf = 0; hf < 2; hf++) {
                float m = -1e30f;
                #pragma unroll
                for (int nt = 0; nt < 7; nt++) {
                    m = fmaxf(m, sc[mt][nt][hf*2+0]);
                    m = fmaxf(m, sc[mt][nt][hf*2+1]);
                }
                m = fmaxf(m, __shfl_xor_sync(0xffffffffu, m, 1));
                m = fmaxf(m, __shfl_xor_sync(0xffffffffu, m, 2));
                float s = 0.f;
                #pragma unroll
                for (int nt = 0; nt < 7; nt++) {
                    float e0 = __expf(sc[mt][nt][hf*2+0] - m);
                    float e1 = __expf(sc[mt][nt][hf*2+1] - m);
                    sc[mt][nt][hf*2+0] = e0;
                    sc[mt][nt][hf*2+1] = e1;
                    s += e0 + e1;
                }
                s += __shfl_xor_sync(0xffffffffu, s, 1);
                s += __shfl_xor_sync(0xffffffffu, s, 2);
                const float inv = __frcp_rn(s);
                #pragma unroll
                for (int nt = 0; nt < 7; nt++) {
                    sc[mt][nt][hf*2+0] *= inv;
                    sc[mt][nt][hf*2+1] *= inv;
                }
            }
        }

        // AV per 16-row m-tile
        float* Pw = Pb + w * PW_F;
        const float4* Pf = (const float4*)Pw;
        const float2* Vf = (const float2*)vs;
        #pragma unroll 1
        for (int mt = 0; mt < 2; mt++) {
            #pragma unroll
            for (int nt = 0; nt < 7; nt++) {
                const int pc = nt*8 + 2*tig;
                Pw[slotP(g,     pc)]     = tf32r(sc[mt][nt][0]);
                Pw[slotP(g,     pc + 1)] = tf32r(sc[mt][nt][1]);
                Pw[slotP(g + 8, pc)]     = tf32r(sc[mt][nt][2]);
                Pw[slotP(g + 8, pc + 1)] = tf32r(sc[mt][nt][3]);
            }
            __syncwarp();

            float o[4][4];
            #pragma unroll
            for (int nv = 0; nv < 4; nv++)
                #pragma unroll
                for (int e = 0; e < 4; e++) o[nv][e] = 0.f;

            #pragma unroll
            for (int kk = 0; kk < 7; kk++) {
                float4 a4 = Pf[kk*32 + lane];
                #pragma unroll
                for (int nv = 0; nv < 4; nv++) {
                    float2 b2 = Vf[(kk*24 + (hb >> 3) + nv)*32 + lane];
                    mma4(o[nv], a4, b2);
                }
            }

            #pragma unroll
            for (int nv = 0; nv < 4; nv++) {
                const int c0 = hb + nv*8 + 2*tig;
                const int r0 = (half*2 + mt)*16 + g;
                xs[slotA(r0,     c0)]     = tf32r(o[nv][0]);
                xs[slotA(r0,     c0 + 1)] = tf32r(o[nv][1]);
                xs[slotA(r0 + 8, c0)]     = tf32r(o[nv][2]);
                xs[slotA(r0 + 8, c0 + 1)] = tf32r(o[nv][3]);
            }
            __syncwarp();
        }
    }
    __syncthreads();

    // ---- output projection: warp owns 16 cols (2 nt) ----
    {
        float acc[4][2][4];
        #pragma unroll
        for (int mt = 0; mt < 4; mt++)
            #pragma unroll
            for (int nt = 0; nt < 2; nt++)
                #pragma unroll
                for (int e = 0; e < 4; e++) acc[mt][nt][e] = 0.f;

        const float4* Af = (const float4*)xs;
        const float2* Pf = (const float2*)g_Pt;
        #pragma unroll 4
        for (int kk = 0; kk < 24; kk++) {
            float4 a4[4];
            #pragma unroll
            for (int mt = 0; mt < 4; mt++) a4[mt] = Af[(kk*4 + mt)*32 + lane];
            #pragma unroll
            for (int nt = 0; nt < 2; nt++) {
                float2 b2 = __ldg(Pf + (kk*24 + w*2 + nt)*32 + lane);
                #pragma unroll
                for (int mt = 0; mt < 4; mt++) mma4(acc[mt][nt], a4[mt], b2);
            }
        }

        float* og = out + (size_t)b * (NTOK*DIM);
        #pragma unroll
        for (int nt = 0; nt < 2; nt++) {
            const int j0 = w*16 + nt*8 + 2*tig;
            const float pb0 = __ldg(proj_b + j0);
            const float pb1 = __ldg(proj_b + j0 + 1);
            #pragma unroll
            for (int mt = 0; mt < 4; mt++) {
                #pragma unroll
                for (int hf = 0; hf < 2; hf++) {
                    const int row = mt*16 + g + hf*8;
                    if (row < NTOK) {
                        *(float2*)(og + row*DIM + j0) =
                            make_float2(acc[mt][nt][hf*2+0] + pb0,
                                        acc[mt][nt][hf*2+1] + pb1);
                    }
                }
            }
        }
    }
}

extern "C" void kernel_launch(void* const* d_in, const int* in_sizes, int n_in,
                              void* d_out, int out_size)
{
    const float* x          = (const float*)d_in[0];
    const float* mask       = (const float*)d_in[1];
    const float* qkv_w      = (const float*)d_in[2];
    const float* qkv_b      = (const float*)d_in[3];
    const float* proj_w     = (const float*)d_in[4];
    const float* proj_b     = (const float*)d_in[5];
    const float* bias_table = (const float*)d_in[6];
    const int*   rel_idx    = (const int*)d_in[7];
    float* out = (float*)d_out;

    prep_kernel<<<1024, 256>>>(qkv_w, proj_w, bias_table, rel_idx, mask);

    const int smem_bytes = SM_F * (int)sizeof(float);
    cudaFuncSetAttribute(win_attn4,
                         cudaFuncAttributeMaxDynamicSharedMemorySize, smem_bytes);
    win_attn4<<<4096, NTHR, smem_bytes>>>(x, qkv_b, proj_b, out);
}

// round 6
// speedup vs baseline: 10.5442x; 2.0279x over previous
#include <cuda_runtime.h>
#include <cuda_fp16.h>

#define DIM    192
#define HEADS  6
#define NTOK   49
#define NWIN   64
#define BMS    50
#define NTHR   256      // 8 warps, 2 CTAs/SM

#define NKB    12       // k-blocks of 16 over DIM
// A-pack block = 4 regs * 33 = 132 u32 ; B-pack block = 2*33 = 66 u32
#define XS_U   (NKB*4*132)     // 6336
#define KS_U   (NKB*7*66)      // 5544
#define VS_U   (4*24*66)       // 6336
#define PB_U   (4*132)         // 528 per warp
#define SM_U   (XS_U + KS_U + VS_U + 8*PB_U)   // 22440 u32 = 89,760 B

__device__ unsigned g_Wh[12*72*2*32];            // qkv_w fp16 B-frag packed
__device__ unsigned g_Ph[12*24*2*32];            // proj_w fp16 B-frag packed
__device__ float    g_bm[NWIN*HEADS*NTOK*BMS];   // bias+mask combined (fp32)

__device__ __forceinline__ unsigned f2h2(float x, float y) {
    __half2 h = __floats2half2_rn(x, y);
    return *(unsigned*)&h;
}

__device__ __forceinline__ void mmaf16(float d[4], const unsigned a[4], const unsigned b[2]) {
    asm volatile(
        "mma.sync.aligned.m16n8k16.row.col.f32.f16.f16.f32 "
        "{%0,%1,%2,%3}, {%4,%5,%6,%7}, {%8,%9}, {%0,%1,%2,%3};\n"
        : "+f"(d[0]), "+f"(d[1]), "+f"(d[2]), "+f"(d[3])
        : "r"(a[0]), "r"(a[1]), "r"(a[2]), "r"(a[3]), "r"(b[0]), "r"(b[1]));
}

// A-pack: addr = (kblk*4+mt)*132 + r*33 + lane ; value (row,col):
// r = ((row>>3)&1) + 2*((col>>3)&1), lane=(row&7)*4+((col>>1)&3), half=col&1.
__device__ __forceinline__ void a_load(const unsigned* base, int kblk, int mt, int lane, unsigned a[4]) {
    const unsigned* p = base + (kblk*4 + mt)*132 + lane;
    a[0] = p[0]; a[1] = p[33]; a[2] = p[66]; a[3] = p[99];
}
__device__ __forceinline__ void a_store(unsigned* base, int row, int col, unsigned h2) {
    int r = ((row >> 3) & 1) + 2*((col >> 3) & 1);
    base[((col >> 4)*4 + (row >> 4))*132 + r*33 + ((row & 7)*4 + ((col >> 1) & 3))] = h2;
}
// B-pack: addr = (kblk*NT+nt)*66 + rb*33 + lane ; value B[k][n]:
// rb=((k>>3)&1), lane=(n&7)*4+((k>>1)&3), half=k&1.
__device__ __forceinline__ void b_load(const unsigned* base, int NT, int kblk, int nt, int lane, unsigned b[2]) {
    const unsigned* p = base + (kblk*NT + nt)*66 + lane;
    b[0] = p[0]; b[1] = p[33];
}

// ---------------- prep kernel ----------------
__global__ void prep_kernel(const float* __restrict__ qkv_w,
                            const float* __restrict__ proj_w,
                            const float* __restrict__ bias_table,
                            const int*   __restrict__ rel_idx,
                            const float* __restrict__ mask)
{
    const int NWE = 96*576, NPE = 96*192, NBE = NWIN*HEADS*NTOK*NTOK;
    for (int idx = blockIdx.x*blockDim.x + threadIdx.x;
         idx < NWE + NPE + NBE; idx += gridDim.x*blockDim.x) {
        if (idx < NWE) {                       // qkv_w: k-pairs x 576 n
            int kp = idx / 576, n = idx % 576;
            int k = 2*kp;
            int s = (((k >> 4)*72 + (n >> 3))*2 + ((k >> 3) & 1))*32
                    + ((n & 7)*4 + ((k >> 1) & 3));
            g_Wh[s] = f2h2(qkv_w[n*192 + k], qkv_w[n*192 + k + 1]);
        } else if (idx < NWE + NPE) {          // proj_w: k-pairs x 192 n
            int t = idx - NWE;
            int kp = t / 192, n = t % 192;
            int k = 2*kp;
            int s = (((k >> 4)*24 + (n >> 3))*2 + ((k >> 3) & 1))*32
                    + ((n & 7)*4 + ((k >> 1) & 3));
            g_Ph[s] = f2h2(proj_w[n*192 + k], proj_w[n*192 + k + 1]);
        } else {
            int t = idx - NWE - NPE;
            int win = t / (HEADS*NTOK*NTOK);
            int r   = t % (HEADS*NTOK*NTOK);
            int h = r / (NTOK*NTOK);
            int e = r % (NTOK*NTOK);
            int i = e / NTOK, j = e % NTOK;
            g_bm[((win*HEADS + h)*NTOK + i)*BMS + j] =
                bias_table[rel_idx[e]*HEADS + h] + mask[win*(NTOK*NTOK) + e];
        }
    }
}

// ---------------- main kernel ----------------
__global__ __launch_bounds__(NTHR, 2)
void win_attn5(const float* __restrict__ x,
               const float* __restrict__ qkv_b,
               const float* __restrict__ proj_b,
               float* __restrict__ out)
{
    extern __shared__ unsigned smu[];
    unsigned* xs = smu;                 // A-pack: x -> Q (in place) -> attn-out (in place)
    unsigned* ks = xs + XS_U;           // B-pack K (tokens as n, 56)
    unsigned* vs = ks + KS_U;           // B-pack V (tokens as k, 64)
    unsigned* Pb = vs + VS_U;           // 8 x per-warp P A-pack (16 x 64)

    const int tid  = threadIdx.x;
    const int w    = tid >> 5;
    const int lane = tid & 31;
    const int g    = lane >> 2;
    const int tig  = lane & 3;
    const int b    = blockIdx.x;
    const float scale = 0.17677669529663687f;

    // zero xs (pad rows) and P buffers (token planes 56..63 stay 0 forever)
    for (int i = tid; i < XS_U; i += NTHR) xs[i] = 0u;
    for (int i = tid; i < 8*PB_U; i += NTHR) Pb[i] = 0u;
    __syncthreads();

    // load x tile (49 x 192) as half2 pairs into A-pack
    const float2* xg = (const float2*)(x + (size_t)b * (NTOK*DIM));
    for (int p = tid; p < NTOK*96; p += NTHR) {
        int row = p / 96, cp = p % 96;
        float2 v = xg[p];
        a_store(xs, row, 2*cp, f2h2(v.x, v.y));
    }
    __syncthreads();

    // ---- QKV GEMM: 3 uniform passes (K, V, Q), 3 n-tiles per warp per pass ----
    for (int pass = 0; pass < 3; pass++) {
        const int t0 = (pass == 0) ? 24 + w*3 : (pass == 1) ? 48 + w*3 : w*3;
        float acc[4][3][4];
        #pragma unroll
        for (int mt = 0; mt < 4; mt++)
            #pragma unroll
            for (int j = 0; j < 3; j++)
                #pragma unroll
                for (int e = 0; e < 4; e++) acc[mt][j][e] = 0.f;

        #pragma unroll 3
        for (int kk = 0; kk < NKB; kk++) {
            unsigned a4[4][4];
            #pragma unroll
            for (int mt = 0; mt < 4; mt++) a_load(xs, kk, mt, lane, a4[mt]);
            #pragma unroll
            for (int j = 0; j < 3; j++) {
                unsigned bb[2];
                const unsigned* p = g_Wh + ((kk*72 + t0 + j)*2)*32 + lane;
                bb[0] = __ldg(p); bb[1] = __ldg(p + 32);
                #pragma unroll
                for (int mt = 0; mt < 4; mt++) mmaf16(acc[mt][j], a4[mt], bb);
            }
        }

        if (pass == 2) __syncthreads();   // all x reads done before Q overwrites xs

        #pragma unroll
        for (int j = 0; j < 3; j++) {
            const int j0 = (t0 + j)*8 + 2*tig;
            const float bj0 = __ldg(qkv_b + j0);
            const float bj1 = __ldg(qkv_b + j0 + 1);
            #pragma unroll
            for (int mt = 0; mt < 4; mt++) {
                #pragma unroll
                for (int hf = 0; hf < 2; hf++) {
                    float v0 = acc[mt][j][hf*2+0] + bj0;
                    float v1 = acc[mt][j][hf*2+1] + bj1;
                    if (pass == 0) {            // K: B[kdim][token]
                        const int token = mt*16 + g + 8*hf;
                        if (token < 56) {
                            const int kd = j0 - 192;
                            ks[((kd >> 4)*7 + (token >> 3))*66 + ((kd >> 3) & 1)*33
                               + (g*4 + tig)] = f2h2(v0, v1);
                        }
                    } else if (pass == 1) {     // V: B[token][vcol] — pair-transpose via shfl
                        unsigned my = f2h2(v0, v1);
                        unsigned pt = __shfl_xor_sync(0xffffffffu, my, 4);
                        unsigned h2 = (g & 1) ? ((pt >> 16) | (my & 0xFFFF0000u))
                                              : ((my & 0xFFFFu) | (pt << 16));
                        const int n = (j0 - 384) + (g & 1);
                        vs[(mt*24 + (n >> 3))*66 + hf*33
                           + ((n & 7)*4 + ((g >> 1) & 3))] = h2;
                    } else {                    // Q (scaled) into xs in place
                        a_store(xs, mt*16 + g + 8*hf, j0, f2h2(v0*scale, v1*scale));
                    }
                }
            }
        }
    }
    __syncthreads();

    // ---- attention: 24 tasks (head x 16-row quarter), 3 per warp ----
    {
        unsigned* Pw = Pb + w * PB_U;
        #pragma unroll 1
        for (int it = 0; it < 3; it++) {
            const int t = w + it*8;
            const int h = t >> 2;
            const int q = t & 3;

            float sc[7][4];
            #pragma unroll
            for (int nt = 0; nt < 7; nt++)
                #pragma unroll
                for (int e = 0; e < 4; e++) sc[nt][e] = 0.f;

            #pragma unroll
            for (int kk = 0; kk < 2; kk++) {
                const int kb = 2*h + kk;
                unsigned a4[4];
                a_load(xs, kb, q, lane, a4);
                #pragma unroll
                for (int nt = 0; nt < 7; nt++) {
                    unsigned bb[2];
                    b_load(ks, 7, kb, nt, lane, bb);
                    mmaf16(sc[nt], a4, bb);
                }
            }

            // bias+mask, pad -> -1e30
            const float2* bmp = (const float2*)(g_bm
                              + (size_t)((b & (NWIN-1))*HEADS + h) * NTOK * BMS);
            const int i0 = q*16 + g;
            #pragma unroll
            for (int nt = 0; nt < 7; nt++) {
                const int j0 = nt*8 + 2*tig;
                float2 u0 = make_float2(0.f, 0.f), u1 = u0;
                if (i0 < NTOK && j0 < NTOK)   u0 = __ldg(bmp + (i0*BMS + j0)/2);
                if (i0+8 < NTOK && j0 < NTOK) u1 = __ldg(bmp + ((i0+8)*BMS + j0)/2);
                sc[nt][0] = (i0   < NTOK && j0   < NTOK) ? sc[nt][0] + u0.x : -1e30f;
                sc[nt][1] = (i0   < NTOK && j0+1 < NTOK) ? sc[nt][1] + u0.y : -1e30f;
                sc[nt][2] = (i0+8 < NTOK && j0   < NTOK) ? sc[nt][2] + u1.x : -1e30f;
                sc[nt][3] = (i0+8 < NTOK && j0+1 < NTOK) ? sc[nt][3] + u1.y : -1e30f;
            }

            // softmax (row owned by quad)
            #pragma unroll
            for (int hf = 0; hf < 2; hf++) {
                float m = -1e30f;
                #pragma unroll
                for (int nt = 0; nt < 7; nt++) {
                    m = fmaxf(m, sc[nt][hf*2+0]);
                    m = fmaxf(m, sc[nt][hf*2+1]);
                }
                m = fmaxf(m, __shfl_xor_sync(0xffffffffu, m, 1));
                m = fmaxf(m, __shfl_xor_sync(0xffffffffu, m, 2));
                float s = 0.f;
                #pragma unroll
                for (int nt = 0; nt < 7; nt++) {
                    float e0 = __expf(sc[nt][hf*2+0] - m);
                    float e1 = __expf(sc[nt][hf*2+1] - m);
                    sc[nt][hf*2+0] = e0; sc[nt][hf*2+1] = e1;
                    s += e0 + e1;
                }
                s += __shfl_xor_sync(0xffffffffu, s, 1);
                s += __shfl_xor_sync(0xffffffffu, s, 2);
                const float inv = __frcp_rn(s);
                #pragma unroll
                for (int nt = 0; nt < 7; nt++) {
                    sc[nt][hf*2+0] *= inv; sc[nt][hf*2+1] *= inv;
                }
            }

            // write P into per-warp A-pack (16 rows x 64 token-cols)
            __syncwarp();
            #pragma unroll
            for (int nt = 0; nt < 7; nt++) {
                const int j0 = nt*8 + 2*tig;
                const int kb = j0 >> 4;
                const int r0 = 2*((j0 >> 3) & 1);
                Pw[kb*132 + r0*33     + (g*4 + tig)] = f2h2(sc[nt][0], sc[nt][1]);
                Pw[kb*132 + (r0+1)*33 + (g*4 + tig)] = f2h2(sc[nt][2], sc[nt][3]);
            }
            __syncwarp();

            // AV: P (16 x 64) x V (64 x 32 head cols)
            float o[4][4];
            #pragma unroll
            for (int nv = 0; nv < 4; nv++)
                #pragma unroll
                for (int e = 0; e < 4; e++) o[nv][e] = 0.f;

            #pragma unroll
            for (int kb = 0; kb < 4; kb++) {
                unsigned a4[4];
                const unsigned* p = Pw + kb*132 + lane;
                a4[0] = p[0]; a4[1] = p[33]; a4[2] = p[66]; a4[3] = p[99];
                #pragma unroll
                for (int nv = 0; nv < 4; nv++) {
                    unsigned bb[2];
                    b_load(vs, 24, kb, 4*h + nv, lane, bb);
                    mmaf16(o[nv], a4, bb);
                }
            }

            __syncwarp();
            #pragma unroll
            for (int nv = 0; nv < 4; nv++) {
                const int c0 = 32*h + nv*8 + 2*tig;
                a_store(xs, q*16 + g,     c0, f2h2(o[nv][0], o[nv][1]));
                a_store(xs, q*16 + g + 8, c0, f2h2(o[nv][2], o[nv][3]));
            }
            __syncwarp();
        }
    }
    __syncthreads();

    // ---- output projection: 3 n-tiles per warp ----
    {
        float acc[4][3][4];
        #pragma unroll
        for (int mt = 0; mt < 4; mt++)
            #pragma unroll
            for (int nt = 0; nt < 3; nt++)
                #pragma unroll
                for (int e = 0; e < 4; e++) acc[mt][nt][e] = 0.f;

        #pragma unroll 3
        for (int kk = 0; kk < NKB; kk++) {
            unsigned a4[4][4];
            #pragma unroll
            for (int mt = 0; mt < 4; mt++) a_load(xs, kk, mt, lane, a4[mt]);
            #pragma unroll
            for (int nt = 0; nt < 3; nt++) {
                unsigned bb[2];
                const unsigned* p = g_Ph + ((kk*24 + w*3 + nt)*2)*32 + lane;
                bb[0] = __ldg(p); bb[1] = __ldg(p + 32);
                #pragma unroll
                for (int mt = 0; mt < 4; mt++) mmaf16(acc[mt][nt], a4[mt], bb);
            }
        }

        float* og = out + (size_t)b * (NTOK*DIM);
        #pragma unroll
        for (int nt = 0; nt < 3; nt++) {
            const int j0 = (w*3 + nt)*8 + 2*tig;
            const float pb0 = __ldg(proj_b + j0);
            const float pb1 = __ldg(proj_b + j0 + 1);
            #pragma unroll
            for (int mt = 0; mt < 4; mt++) {
                #pragma unroll
                for (int hf = 0; hf < 2; hf++) {
                    const int row = mt*16 + g + hf*8;
                    if (row < NTOK) {
                        *(float2*)(og + row*DIM + j0) =
                            make_float2(acc[mt][nt][hf*2+0] + pb0,
                                        acc[mt][nt][hf*2+1] + pb1);
                    }
                }
            }
        }
    }
}

extern "C" void kernel_launch(void* const* d_in, const int* in_sizes, int n_in,
                              void* d_out, int out_size)
{
    const float* x          = (const float*)d_in[0];
    const float* mask       = (const float*)d_in[1];
    const float* qkv_w      = (const float*)d_in[2];
    const float* qkv_b      = (const float*)d_in[3];
    const float* proj_w     = (const float*)d_in[4];
    const float* proj_b     = (const float*)d_in[5];
    const float* bias_table = (const float*)d_in[6];
    const int*   rel_idx    = (const int*)d_in[7];
    float* out = (float*)d_out;

    prep_kernel<<<1024, 256>>>(qkv_w, proj_w, bias_table, rel_idx, mask);

    const int smem_bytes = SM_U * (int)sizeof(unsigned);
    cudaFuncSetAttribute(win_attn5,
                         cudaFuncAttributeMaxDynamicSharedMemorySize, smem_bytes);
    win_attn5<<<4096, NTHR, smem_bytes>>>(x, qkv_b, proj_b, out);
}

// round 7
// speedup vs baseline: 10.8739x; 1.0313x over previous
#include <cuda_runtime.h>
#include <cuda_fp16.h>

#define DIM    192
#define HEADS  6
#define NTOK   49
#define NWIN   64
#define BMS    50
#define NTHR   256      // 8 warps, 2 CTAs/SM

#define NKB    12
// A block (16 rows x 16 k) = 32 units x 16B = 128 u32 ; B block (8 n x 16 k) = 64 u32
#define XS_U   (NKB*4*128)     // 6144
#define KS_U   (NKB*7*64)      // 5376
#define VS_U   (4*24*64)       // 6144
#define PB_U   (4*128)         // 512 per warp
#define SM_U   (XS_U + KS_U + VS_U + 8*PB_U)   // 21760 u32 = 87,040 B

__device__ unsigned g_Wh[12*72*32*2];            // qkv_w fp16, B-frag pair-packed (LDG.64)
__device__ unsigned g_Ph[12*24*32*2];            // proj_w fp16, B-frag pair-packed
__device__ float    g_bm[NWIN*HEADS*NTOK*BMS];   // bias+mask combined (fp32)

__device__ __forceinline__ unsigned f2h2(float x, float y) {
    __half2 h = __floats2half2_rn(x, y);
    return *(unsigned*)&h;
}

__device__ __forceinline__ void mmaf16(float d[4], const unsigned a[4], const unsigned b[2]) {
    asm volatile(
        "mma.sync.aligned.m16n8k16.row.col.f32.f16.f16.f32 "
        "{%0,%1,%2,%3}, {%4,%5,%6,%7}, {%8,%9}, {%0,%1,%2,%3};\n"
        : "+f"(d[0]), "+f"(d[1]), "+f"(d[2]), "+f"(d[3])
        : "r"(a[0]), "r"(a[1]), "r"(a[2]), "r"(a[3]), "r"(b[0]), "r"(b[1]));
}

__device__ __forceinline__ void ldsm_x4(unsigned a[4], const unsigned* p) {
    unsigned addr = (unsigned)__cvta_generic_to_shared(p);
    asm volatile("ldmatrix.sync.aligned.m8n8.x4.shared.b16 {%0,%1,%2,%3}, [%4];"
                 : "=r"(a[0]), "=r"(a[1]), "=r"(a[2]), "=r"(a[3]) : "r"(addr));
}
__device__ __forceinline__ void ldsm_x2(unsigned b[2], const unsigned* p) {
    unsigned addr = (unsigned)__cvta_generic_to_shared(p);
    asm volatile("ldmatrix.sync.aligned.m8n8.x2.shared.b16 {%0,%1}, [%2];"
                 : "=r"(b[0]), "=r"(b[1]) : "r"(addr));
}

// A block layout: unit u = ((col>>3)&1)*16 + (row&15), 16B contiguous in k.
// ldmatrix.x4 with thread t -> unit t reproduces the mma A fragment order.
__device__ __forceinline__ void a_load(const unsigned* base, int kblk, int mt, int lane, unsigned a[4]) {
    ldsm_x4(a, base + (kblk*4 + mt)*128 + lane*4);
}
__device__ __forceinline__ void a_store(unsigned* base, int row, int col, unsigned h2) {
    base[((col >> 4)*4 + (row >> 4))*128
         + (((col >> 3) & 1)*16 + (row & 15))*4 + ((col >> 1) & 3)] = h2;
}
// B block layout: unit u = ((k>>3)&1)*8 + (n&7). ldmatrix.x2 -> b0 (k0-7), b1 (k8-15).
__device__ __forceinline__ void b_load(const unsigned* base, int NT, int kblk, int nt, int lane, unsigned b[2]) {
    ldsm_x2(b, base + (kblk*NT + nt)*64 + (lane & 15)*4);
}
__device__ __forceinline__ int b_slot(int NT, int kblk, int nt, int k, int n) {
    return (kblk*NT + nt)*64 + (((k >> 3) & 1)*8 + (n & 7))*4 + ((k >> 1) & 3);
}

// ---------------- prep kernel ----------------
__global__ void prep_kernel(const float* __restrict__ qkv_w,
                            const float* __restrict__ proj_w,
                            const float* __restrict__ bias_table,
                            const int*   __restrict__ rel_idx,
                            const float* __restrict__ mask)
{
    const int NWE = 96*576, NPE = 96*192, NBE = NWIN*HEADS*NTOK*NTOK;
    for (int idx = blockIdx.x*blockDim.x + threadIdx.x;
         idx < NWE + NPE + NBE; idx += gridDim.x*blockDim.x) {
        if (idx < NWE) {                       // qkv_w: k-pairs x 576 n
            int kp = idx / 576, n = idx % 576;
            int k = 2*kp;
            int s = (((k >> 4)*72 + (n >> 3))*32 + ((n & 7)*4 + ((k >> 1) & 3)))*2
                    + ((k >> 3) & 1);
            g_Wh[s] = f2h2(qkv_w[n*192 + k], qkv_w[n*192 + k + 1]);
        } else if (idx < NWE + NPE) {          // proj_w
            int t = idx - NWE;
            int kp = t / 192, n = t % 192;
            int k = 2*kp;
            int s = (((k >> 4)*24 + (n >> 3))*32 + ((n & 7)*4 + ((k >> 1) & 3)))*2
                    + ((k >> 3) & 1);
            g_Ph[s] = f2h2(proj_w[n*192 + k], proj_w[n*192 + k + 1]);
        } else {
            int t = idx - NWE - NPE;
            int win = t / (HEADS*NTOK*NTOK);
            int r   = t % (HEADS*NTOK*NTOK);
            int h = r / (NTOK*NTOK);
            int e = r % (NTOK*NTOK);
            int i = e / NTOK, j = e % NTOK;
            g_bm[((win*HEADS + h)*NTOK + i)*BMS + j] =
                bias_table[rel_idx[e]*HEADS + h] + mask[win*(NTOK*NTOK) + e];
        }
    }
}

// ---------------- main kernel ----------------
__global__ __launch_bounds__(NTHR, 2)
void win_attn6(const float* __restrict__ x,
               const float* __restrict__ qkv_b,
               const float* __restrict__ proj_b,
               float* __restrict__ out)
{
    extern __shared__ unsigned smu[];
    unsigned* xs = smu;                 // A-pack: x -> Q (in place) -> attn-out (in place)
    unsigned* ks = xs + XS_U;           // B-pack K (tokens as n)
    unsigned* vs = ks + KS_U;           // B-pack V (tokens as k)
    unsigned* Pb = vs + VS_U;           // 8 x per-warp P A-pack (16 x 64)

    const int tid  = threadIdx.x;
    const int w    = tid >> 5;
    const int lane = tid & 31;
    const int g    = lane >> 2;
    const int tig  = lane & 3;
    const int b    = blockIdx.x;
    const float scale = 0.17677669529663687f;

    // zero xs pad rows, vs (tokens 56-63 never written), P buffers
    for (int i = tid; i < XS_U; i += NTHR) xs[i] = 0u;
    for (int i = tid; i < VS_U; i += NTHR) vs[i] = 0u;
    for (int i = tid; i < 8*PB_U; i += NTHR) Pb[i] = 0u;
    __syncthreads();

    // load x tile (49 x 192) as half2 pairs into A-pack
    const float2* xg = (const float2*)(x + (size_t)b * (NTOK*DIM));
    for (int p = tid; p < NTOK*96; p += NTHR) {
        int row = p / 96, cp = p % 96;
        float2 v = xg[p];
        a_store(xs, row, 2*cp, f2h2(v.x, v.y));
    }
    __syncthreads();

    // ---- QKV GEMM: 3 uniform passes (K, V, Q), 3 n-tiles per warp per pass ----
    for (int pass = 0; pass < 3; pass++) {
        const int t0 = (pass == 0) ? 24 + w*3 : (pass == 1) ? 48 + w*3 : w*3;
        float acc[4][3][4];
        #pragma unroll
        for (int mt = 0; mt < 4; mt++)
            #pragma unroll
            for (int j = 0; j < 3; j++)
                #pragma unroll
                for (int e = 0; e < 4; e++) acc[mt][j][e] = 0.f;

        #pragma unroll 3
        for (int kk = 0; kk < NKB; kk++) {
            unsigned a4[4][4];
            #pragma unroll
            for (int mt = 0; mt < 4; mt++) a_load(xs, kk, mt, lane, a4[mt]);
            #pragma unroll
            for (int j = 0; j < 3; j++) {
                uint2 bb = __ldg((const uint2*)g_Wh + (kk*72 + t0 + j)*32 + lane);
                unsigned bArr[2] = {bb.x, bb.y};
                #pragma unroll
                for (int mt = 0; mt < 4; mt++) mmaf16(acc[mt][j], a4[mt], bArr);
            }
        }

        if (pass == 2) __syncthreads();   // all x reads done before Q overwrites xs

        #pragma unroll
        for (int j = 0; j < 3; j++) {
            const int j0 = (t0 + j)*8 + 2*tig;
            const float bj0 = __ldg(qkv_b + j0);
            const float bj1 = __ldg(qkv_b + j0 + 1);
            #pragma unroll
            for (int mt = 0; mt < 4; mt++) {
                #pragma unroll
                for (int hf = 0; hf < 2; hf++) {
                    float v0 = acc[mt][j][hf*2+0] + bj0;
                    float v1 = acc[mt][j][hf*2+1] + bj1;
                    if (pass == 0) {            // K: B[kdim][token]
                        const int token = mt*16 + g + 8*hf;
                        if (token < 56) {
                            const int kd = j0 - 192;
                            ks[b_slot(7, kd >> 4, token >> 3, kd, token)] = f2h2(v0, v1);
                        }
                    } else if (pass == 1) {     // V: B[token][vcol] — pair-transpose via shfl
                        unsigned my = f2h2(v0, v1);
                        unsigned pt = __shfl_xor_sync(0xffffffffu, my, 4);
                        unsigned h2 = (g & 1) ? ((pt >> 16) | (my & 0xFFFF0000u))
                                              : ((my & 0xFFFFu) | (pt << 16));
                        const int n   = (j0 - 384) + (g & 1);
                        const int tok = mt*16 + g + 8*hf;
                        vs[b_slot(24, tok >> 4, n >> 3, tok, n)] = h2;
                    } else {                    // Q (scaled) into xs in place
                        a_store(xs, mt*16 + g + 8*hf, j0, f2h2(v0*scale, v1*scale));
                    }
                }
            }
        }
    }
    __syncthreads();

    // ---- attention: 24 tasks (head x 16-row quarter), 3 per warp ----
    {
        unsigned* Pw = Pb + w * PB_U;
        #pragma unroll 1
        for (int it = 0; it < 3; it++) {
            const int t = w + it*8;
            const int h = t >> 2;
            const int q = t & 3;

            float sc[7][4];
            #pragma unroll
            for (int nt = 0; nt < 7; nt++)
                #pragma unroll
                for (int e = 0; e < 4; e++) sc[nt][e] = 0.f;

            #pragma unroll
            for (int kk = 0; kk < 2; kk++) {
                const int kb = 2*h + kk;
                unsigned a4[4];
                a_load(xs, kb, q, lane, a4);
                #pragma unroll
                for (int nt = 0; nt < 7; nt++) {
                    unsigned bb[2];
                    b_load(ks, 7, kb, nt, lane, bb);
                    mmaf16(sc[nt], a4, bb);
                }
            }

            // bias+mask, pad -> -1e30
            const float2* bmp = (const float2*)(g_bm
                              + (size_t)((b & (NWIN-1))*HEADS + h) * NTOK * BMS);
            const int i0 = q*16 + g;
            #pragma unroll
            for (int nt = 0; nt < 7; nt++) {
                const int j0 = nt*8 + 2*tig;
                float2 u0 = make_float2(0.f, 0.f), u1 = u0;
                if (i0 < NTOK && j0 < NTOK)   u0 = __ldg(bmp + (i0*BMS + j0)/2);
                if (i0+8 < NTOK && j0 < NTOK) u1 = __ldg(bmp + ((i0+8)*BMS + j0)/2);
                sc[nt][0] = (i0   < NTOK && j0   < NTOK) ? sc[nt][0] + u0.x : -1e30f;
                sc[nt][1] = (i0   < NTOK && j0+1 < NTOK) ? sc[nt][1] + u0.y : -1e30f;
                sc[nt][2] = (i0+8 < NTOK && j0   < NTOK) ? sc[nt][2] + u1.x : -1e30f;
                sc[nt][3] = (i0+8 < NTOK && j0+1 < NTOK) ? sc[nt][3] + u1.y : -1e30f;
            }

            // softmax (row owned by quad)
            #pragma unroll
            for (int hf = 0; hf < 2; hf++) {
                float m = -1e30f;
                #pragma unroll
                for (int nt = 0; nt < 7; nt++) {
                    m = fmaxf(m, sc[nt][hf*2+0]);
                    m = fmaxf(m, sc[nt][hf*2+1]);
                }
                m = fmaxf(m, __shfl_xor_sync(0xffffffffu, m, 1));
                m = fmaxf(m, __shfl_xor_sync(0xffffffffu, m, 2));
                float s = 0.f;
                #pragma unroll
                for (int nt = 0; nt < 7; nt++) {
                    float e0 = __expf(sc[nt][hf*2+0] - m);
                    float e1 = __expf(sc[nt][hf*2+1] - m);
                    sc[nt][hf*2+0] = e0; sc[nt][hf*2+1] = e1;
                    s += e0 + e1;
                }
                s += __shfl_xor_sync(0xffffffffu, s, 1);
                s += __shfl_xor_sync(0xffffffffu, s, 2);
                const float inv = __frcp_rn(s);
                #pragma unroll
                for (int nt = 0; nt < 7; nt++) {
                    sc[nt][hf*2+0] *= inv; sc[nt][hf*2+1] *= inv;
                }
            }

            // write P into per-warp A-pack (16 rows x 64 token-cols)
            __syncwarp();
            #pragma unroll
            for (int nt = 0; nt < 7; nt++) {
                const int j0 = nt*8 + 2*tig;
                const int kb = j0 >> 4;
                const int kh = (j0 >> 3) & 1;
                Pw[kb*128 + (kh*16 + g)*4     + tig] = f2h2(sc[nt][0], sc[nt][1]);
                Pw[kb*128 + (kh*16 + g + 8)*4 + tig] = f2h2(sc[nt][2], sc[nt][3]);
            }
            __syncwarp();

            // AV: P (16 x 64) x V (64 x 32 head cols)
            float o[4][4];
            #pragma unroll
            for (int nv = 0; nv < 4; nv++)
                #pragma unroll
                for (int e = 0; e < 4; e++) o[nv][e] = 0.f;

            #pragma unroll
            for (int kb = 0; kb < 4; kb++) {
                unsigned a4[4];
                ldsm_x4(a4, Pw + kb*128 + lane*4);
                #pragma unroll
                for (int nv = 0; nv < 4; nv++) {
                    unsigned bb[2];
                    b_load(vs, 24, kb, 4*h + nv, lane, bb);
                    mmaf16(o[nv], a4, bb);
                }
            }

            __syncwarp();
            #pragma unroll
            for (int nv = 0; nv < 4; nv++) {
                const int c0 = 32*h + nv*8 + 2*tig;
                a_store(xs, q*16 + g,     c0, f2h2(o[nv][0], o[nv][1]));
                a_store(xs, q*16 + g + 8, c0, f2h2(o[nv][2], o[nv][3]));
            }
            __syncwarp();
        }
    }
    __syncthreads();

    // ---- output projection: 3 n-tiles per warp ----
    {
        float acc[4][3][4];
        #pragma unroll
        for (int mt = 0; mt < 4; mt++)
            #pragma unroll
            for (int nt = 0; nt < 3; nt++)
                #pragma unroll
                for (int e = 0; e < 4; e++) acc[mt][nt][e] = 0.f;

        #pragma unroll 3
        for (int kk = 0; kk < NKB; kk++) {
            unsigned a4[4][4];
            #pragma unroll
            for (int mt = 0; mt < 4; mt++) a_load(xs, kk, mt, lane, a4[mt]);
            #pragma unroll
            for (int nt = 0; nt < 3; nt++) {
                uint2 bb = __ldg((const uint2*)g_Ph + (kk*24 + w*3 + nt)*32 + lane);
                unsigned bArr[2] = {bb.x, bb.y};
                #pragma unroll
                for (int mt = 0; mt < 4; mt++) mmaf16(acc[mt][nt], a4[mt], bArr);
            }
        }

        float* og = out + (size_t)b * (NTOK*DIM);
        #pragma unroll
        for (int nt = 0; nt < 3; nt++) {
            const int j0 = (w*3 + nt)*8 + 2*tig;
            const float pb0 = __ldg(proj_b + j0);
            const float pb1 = __ldg(proj_b + j0 + 1);
            #pragma unroll
            for (int mt = 0; mt < 4; mt++) {
                #pragma unroll
                for (int hf = 0; hf < 2; hf++) {
                    const int row = mt*16 + g + hf*8;
                    if (row < NTOK) {
                        *(float2*)(og + row*DIM + j0) =
                            make_float2(acc[mt][nt][hf*2+0] + pb0,
                                        acc[mt][nt][hf*2+1] + pb1);
                    }
                }
            }
        }
    }
}

extern "C" void kernel_launch(void* const* d_in, const int* in_sizes, int n_in,
                              void* d_out, int out_size)
{
    const float* x          = (const float*)d_in[0];
    const float* mask       = (const float*)d_in[1];
    const float* qkv_w      = (const float*)d_in[2];
    const float* qkv_b      = (const float*)d_in[3];
    const float* proj_w     = (const float*)d_in[4];
    const float* proj_b     = (const float*)d_in[5];
    const float* bias_table = (const float*)d_in[6];
    const int*   rel_idx    = (const int*)d_in[7];
    float* out = (float*)d_out;

    prep_kernel<<<1024, 256>>>(qkv_w, proj_w, bias_table, rel_idx, mask);

    const int smem_bytes = SM_U * (int)sizeof(unsigned);
    cudaFuncSetAttribute(win_attn6,
                         cudaFuncAttributeMaxDynamicSharedMemorySize, smem_bytes);
    win_attn6<<<4096, NTHR, smem_bytes>>>(x, qkv_b, proj_b, out);
}